// round 4
// baseline (speedup 1.0000x reference)
#include <cuda_runtime.h>
#include <stdint.h>

#define BATCH 1024
#define KSEL  64
#define IFEAT 4096
#define OFEAT 4096
#define SLAB_BYTES (4096 * 8 * 4)   // 131072

// Device scratch (static device globals; no runtime alloc).
// ent layout is K-MAJOR: ent[k*1024 + b] = (x bits, swizzled word-offset)
__device__ uint2 g_ent[(size_t)KSEL * BATCH];       // 512 KB
__device__ float g_y[(size_t)BATCH * OFEAT];        // 16 MB

// ---------------------------------------------------------------------------
// Prep: bake per-(b,k) entry. Offset pre-encodes c*8 plus the 16B slot swizzle
// for lane-half h=0; lane-half 1 recovers its slot with a single XOR of bit 2.
// ---------------------------------------------------------------------------
__global__ void prep_kernel(const float* __restrict__ x,
                            const int*   __restrict__ idx)
{
    int t = blockIdx.x * 256 + threadIdx.x;   // t = b*64 + k (coalesced reads)
    if (t >= BATCH * KSEL) return;
    int b = t >> 6, k = t & 63;
    int c = idx[t];
    unsigned off = (unsigned)(c * 8) + ((((unsigned)c >> 2) & 1u) << 2);
    g_ent[(size_t)k * BATCH + b] = make_uint2(__float_as_uint(x[t]), off);
}

// ---------------------------------------------------------------------------
// Main: block (tile, half). Slab = W[o0..o0+8)[0..4096) in smem, stored
// swizzled at 16B-slot granularity: word(c, r) = c*8 + ((((c>>2)&1)^(r>>2))<<2) + (r&3).
// Warp = 16 samples x 2 lane-halves; each lane runs the exact sequential-k
// FMA chain for 4 outputs of its sample (float4 slab read per k), bias last.
// Bit-identical to the reference reduction order.
// ---------------------------------------------------------------------------
__global__ __launch_bounds__(256) void main_kernel(const float* __restrict__ W,
                                                   const float* __restrict__ bias)
{
    extern __shared__ float sw[];   // 4096 cols x 8 outputs, swizzled
    const int tile = blockIdx.x;    // 0..511
    const int o0   = tile * 8;
    const int t    = threadIdx.x;

    // Stage slab: scalar coalesced LDG (warp = 32 consecutive c, one line),
    // swizzled scalar STS (~4-way phases, bounded by the (c>>2)&1 split).
#pragma unroll 4
    for (int i = 0; i < 128; ++i) {
        int id = i * 256 + t;
        int r  = id >> 12;          // 0..7
        int c  = id & 4095;
        float v = W[(size_t)(o0 + r) * IFEAT + c];
        int word = c * 8 + (((((unsigned)c >> 2) & 1u) ^ ((unsigned)r >> 2)) << 2) + (r & 3);
        sw[word] = v;
    }
    __syncthreads();

    const int warp = t >> 5;
    const int lane = t & 31;
    const int sl   = lane >> 1;          // sample within warp group (0..15)
    const unsigned hx = (lane & 1) << 2; // lane-half slot XOR
    const float4 bv = reinterpret_cast<const float4*>(bias + o0)[lane & 1];

    const int bbase0 = blockIdx.y * 512 + warp * 16 + sl;

#pragma unroll
    for (int pass = 0; pass < 4; ++pass) {
        const int b = bbase0 + pass * 128;
        float a0 = 0.f, a1 = 0.f, a2 = 0.f, a3 = 0.f;
#pragma unroll 8
        for (int k = 0; k < KSEL; ++k) {
            uint2 ev = g_ent[(size_t)k * BATCH + b];   // warp: one 128B line
            const float4 w4 = *reinterpret_cast<const float4*>(sw + (ev.y ^ hx));
            float xv = __uint_as_float(ev.x);
            a0 = fmaf(xv, w4.x, a0);
            a1 = fmaf(xv, w4.y, a1);
            a2 = fmaf(xv, w4.z, a2);
            a3 = fmaf(xv, w4.w, a3);
        }
        float4 yo = make_float4(a0 + bv.x, a1 + bv.y, a2 + bv.z, a3 + bv.w);
        *reinterpret_cast<float4*>(g_y + (size_t)b * OFEAT + o0 + ((lane & 1) << 2)) = yo;
    }
}

// ---------------------------------------------------------------------------
// Exact top-64 per sample (unchanged, proven rel_err 0.0): monotone keys,
// 4-pass radix select of exact rank-64, stable bitonic (value desc, idx asc).
// ---------------------------------------------------------------------------
__device__ __forceinline__ unsigned f2u(float f) {
    unsigned u = __float_as_uint(f);
    return (u & 0x80000000u) ? ~u : (u | 0x80000000u);
}
__device__ __forceinline__ float u2f(unsigned u) {
    unsigned b = (u & 0x80000000u) ? (u ^ 0x80000000u) : ~u;
    return __uint_as_float(b);
}

__global__ __launch_bounds__(256) void topk_kernel(float* __restrict__ out, int out_size)
{
    __shared__ unsigned su[OFEAT];
    __shared__ unsigned hist[256];
    __shared__ unsigned long long cand[256];
    __shared__ unsigned sh_prefix;
    __shared__ int sh_need;
    __shared__ int ncand;

    const int b = blockIdx.x;
    const int tid = threadIdx.x;

    for (int o4 = tid; o4 < OFEAT / 4; o4 += 256) {
        float4 v = reinterpret_cast<const float4*>(g_y + (size_t)b * OFEAT)[o4];
        su[o4 * 4 + 0] = f2u(v.x);
        su[o4 * 4 + 1] = f2u(v.y);
        su[o4 * 4 + 2] = f2u(v.z);
        su[o4 * 4 + 3] = f2u(v.w);
    }

    unsigned prefix = 0, mask = 0;
    int shift = 24, need = KSEL;
    for (int pass = 0; pass < 4; ++pass) {
        hist[tid] = 0;
        __syncthreads();
        for (int o = tid; o < OFEAT; o += 256) {
            unsigned u = su[o];
            if ((u & mask) == prefix)
                atomicAdd(&hist[(u >> shift) & 255], 1u);
        }
        __syncthreads();
        if (tid == 0) {
            int cum = 0;
            for (int bin = 255; bin >= 0; --bin) {
                cum += (int)hist[bin];
                if (cum >= need) {
                    sh_prefix = prefix | ((unsigned)bin << shift);
                    sh_need   = need - (cum - (int)hist[bin]);
                    break;
                }
            }
        }
        __syncthreads();
        prefix = sh_prefix;
        need   = sh_need;
        mask  |= (0xFFu << shift);
        shift -= 8;
    }
    const unsigned T = prefix;

    if (tid == 0) ncand = 0;
    cand[tid] = 0ull;
    __syncthreads();
    for (int o = tid; o < OFEAT; o += 256) {
        unsigned u = su[o];
        if (u >= T) {
            int p = atomicAdd(&ncand, 1);
            if (p < 256)
                cand[p] = ((unsigned long long)u << 32) | (unsigned)(4095 - o);
        }
    }
    __syncthreads();

    for (int k2 = 2; k2 <= 256; k2 <<= 1) {
        for (int j2 = k2 >> 1; j2 > 0; j2 >>= 1) {
            int i = tid, ixj = tid ^ j2;
            if (ixj > i) {
                bool desc = ((i & k2) == 0);
                unsigned long long a = cand[i], bb = cand[ixj];
                if (desc ? (a < bb) : (a > bb)) { cand[i] = bb; cand[ixj] = a; }
            }
            __syncthreads();
        }
    }

    if (tid < KSEL) {
        unsigned long long key = cand[tid];
        unsigned u = (unsigned)(key >> 32);
        int o = 4095 - (int)(key & 0xFFFFFFFFull);
        int half = out_size >> 1;
        out[(size_t)b * KSEL + tid]        = u2f(u);
        out[(size_t)half + b * KSEL + tid] = (float)o;
    }
}

// ---------------------------------------------------------------------------
extern "C" void kernel_launch(void* const* d_in, const int* in_sizes, int n_in,
                              void* d_out, int out_size)
{
    const float* input  = nullptr;
    const float* weight = nullptr;
    const float* bias   = nullptr;
    const int*   idx    = nullptr;
    for (int i = 0; i < n_in; ++i) {
        if (in_sizes[i] == OFEAT * IFEAT)      weight = (const float*)d_in[i];
        else if (in_sizes[i] == OFEAT)         bias   = (const float*)d_in[i];
        else if (in_sizes[i] == BATCH * KSEL) {
            if (!input) input = (const float*)d_in[i];
            else        idx   = (const int*)d_in[i];
        }
    }

    prep_kernel<<<(BATCH * KSEL) / 256, 256>>>(input, idx);

    cudaFuncSetAttribute(main_kernel,
                         cudaFuncAttributeMaxDynamicSharedMemorySize,
                         SLAB_BYTES);
    main_kernel<<<dim3(OFEAT / 8, 2), 256, SLAB_BYTES>>>(weight, bias);

    topk_kernel<<<BATCH, 256>>>((float*)d_out, out_size);
}

// round 5
// speedup vs baseline: 1.2759x; 1.2759x over previous
#include <cuda_runtime.h>
#include <stdint.h>

#define BATCH 1024
#define KSEL  64
#define IFEAT 4096
#define OFEAT 4096

// Output split: [0, SM_OUTS) via smem-slab path, [SM_OUTS, 4096) via L2 gemv.
#define SM_OUTS   1024
#define SM_TILES  (SM_OUTS / 8)          // 128 tiles of 8 outputs
#define GEMV_OUTS (OFEAT - SM_OUTS)      // 3072
#define GEMV_CHUNK 1024                  // outputs per gemv block (512 thr x float2)
#define GEMV_BLOCKS (BATCH * (GEMV_OUTS / GEMV_CHUNK))   // 3072
#define GRID_X (SM_TILES + GEMV_BLOCKS)  // 3200
#define DYN_SMEM (IFEAT * 8 * 4)         // 128 KB slab

// Device scratch (static device globals; no runtime alloc).
__device__ float g_WT[(size_t)IFEAT * OFEAT];   // transposed W (only cols >= SM_OUTS valid)
__device__ float g_y[(size_t)BATCH * OFEAT];    // dense pre-topk result
__device__ uint2 g_ent[(size_t)BATCH * KSEL];   // sample-major: (x bits, 8c | ((c>>2)&7))

// ---------------------------------------------------------------------------
// Prep: pack per-(b,k) entry for the smem path.
// ---------------------------------------------------------------------------
__global__ void prep_kernel(const float* __restrict__ x,
                            const int*   __restrict__ idx)
{
    int t = blockIdx.x * 256 + threadIdx.x;
    if (t >= BATCH * KSEL) return;
    unsigned c = (unsigned)idx[t];
    g_ent[t] = make_uint2(__float_as_uint(x[t]), (c << 3) | ((c >> 2) & 7u));
}

// ---------------------------------------------------------------------------
// Transpose W rows [SM_OUTS, 4096) -> WT columns (gemv share only).
// ---------------------------------------------------------------------------
__global__ __launch_bounds__(256) void transpose_kernel(const float* __restrict__ W)
{
    __shared__ float t[64][65];
    const int bc = blockIdx.x * 64;            // input-feature
    const int br = SM_OUTS + blockIdx.y * 64;  // output-feature (gemv range)
    const int tid = threadIdx.x;
    const int sub = tid & 15;
    const int grp = tid >> 4;
#pragma unroll
    for (int p = 0; p < 4; ++p) {
        int row = p * 16 + grp;
        int c4  = sub * 4;
        float4 v = *reinterpret_cast<const float4*>(
            W + (size_t)(br + row) * IFEAT + bc + c4);
        t[c4 + 0][row] = v.x;
        t[c4 + 1][row] = v.y;
        t[c4 + 2][row] = v.z;
        t[c4 + 3][row] = v.w;
    }
    __syncthreads();
#pragma unroll
    for (int p = 0; p < 4; ++p) {
        int c  = p * 16 + grp;
        int o4 = sub * 4;
        float4 v = make_float4(t[c][o4], t[c][o4 + 1], t[c][o4 + 2], t[c][o4 + 3]);
        *reinterpret_cast<float4*>(g_WT + (size_t)(bc + c) * OFEAT + br + o4) = v;
    }
}

// ---------------------------------------------------------------------------
// Heterogeneous main kernel: 512 threads/block.
//  - smem blocks (128): tile of 8 outputs, slab = W[o0..o0+8)[0..4096) in smem,
//    swizzled word(c,r) = 8c + (r ^ ((c>>2)&7))  (conflict-free stores,
//    ~2.1-phase loads). Warp = 4 samples x 8 outputs, scalar LDS per FMA.
//  - gemv blocks (3072): 1 sample x 1024 outputs, float2/lane, streaming WT.
// Both paths: identical sequential-k FMA chain, bias added last (bit-exact
// vs reference). Launch order interleaves smem tiles every 8th bid.
// ---------------------------------------------------------------------------
__global__ __launch_bounds__(512, 1) void main_kernel(const float* __restrict__ W,
                                                      const float* __restrict__ x,
                                                      const int*   __restrict__ idx,
                                                      const float* __restrict__ bias)
{
    extern __shared__ float buf[];
    const int bid = blockIdx.x;
    const int t   = threadIdx.x;

    bool is_smem;
    int tile = 0, g = 0;
    if (bid < 1024) {
        is_smem = ((bid & 7) == 0);
        if (is_smem) tile = bid >> 3;
        else         g    = bid - (bid >> 3) - 1;
    } else {
        is_smem = false;
        g = bid - SM_TILES;
    }

    if (is_smem) {
        // ---- smem-slab path ----
        float* sw = buf;                 // 32768 words
        const int o0 = tile * 8;

        // Stage slab: coalesced row reads, swizzled conflict-free stores.
#pragma unroll 4
        for (int i = 0; i < 64; ++i) {
            int id = i * 512 + t;
            int r  = id >> 12;           // 0..7
            int c  = id & 4095;
            float v = W[(size_t)(o0 + r) * IFEAT + c];
            sw[c * 8 + ((r ^ (c >> 2)) & 7)] = v;
        }
        __syncthreads();

        const int warp = t >> 5;
        const int lane = t & 31;
        const int grp  = lane >> 3;      // sample slot within warp (0..3)
        const int r    = lane & 7;       // output within tile
        const float bv = bias[o0 + r];

#pragma unroll 1
        for (int pass = 0; pass < 16; ++pass) {
            const int b = pass * 64 + warp * 4 + grp;
            const uint2* __restrict__ e = g_ent + b * KSEL;
            float a = 0.f;
#pragma unroll 8
            for (int k = 0; k < KSEL; ++k) {
                uint2 ev = __ldg(e + k);
                float wv = sw[(ev.y & ~7u) | ((unsigned)(r ^ ev.y) & 7u)];
                a = fmaf(__uint_as_float(ev.x), wv, a);
            }
            g_y[(size_t)b * OFEAT + o0 + r] = a + bv;
        }
    } else {
        // ---- L2-stream gemv path ----
        float* sx   = buf;
        int*   soff = (int*)(buf + KSEL);

        const int b     = g / (GEMV_OUTS / GEMV_CHUNK);
        const int chunk = g % (GEMV_OUTS / GEMV_CHUNK);
        const int o     = SM_OUTS + chunk * GEMV_CHUNK + t * 2;

        if (t < KSEL) {
            sx[t]   = x[b * KSEL + t];
            soff[t] = idx[b * KSEL + t] * OFEAT;
        }
        __syncthreads();

        float ax = 0.f, ay = 0.f;
#pragma unroll 8
        for (int k = 0; k < KSEL; ++k) {
            const float xv = sx[k];
            const float2 w = *reinterpret_cast<const float2*>(g_WT + soff[k] + o);
            ax = fmaf(xv, w.x, ax);
            ay = fmaf(xv, w.y, ay);
        }
        float2 yo = make_float2(ax + bias[o], ay + bias[o + 1]);
        *reinterpret_cast<float2*>(g_y + (size_t)b * OFEAT + o) = yo;
    }
}

// ---------------------------------------------------------------------------
// Exact top-64 per sample (proven rel_err 0.0).
// ---------------------------------------------------------------------------
__device__ __forceinline__ unsigned f2u(float f) {
    unsigned u = __float_as_uint(f);
    return (u & 0x80000000u) ? ~u : (u | 0x80000000u);
}
__device__ __forceinline__ float u2f(unsigned u) {
    unsigned b = (u & 0x80000000u) ? (u ^ 0x80000000u) : ~u;
    return __uint_as_float(b);
}

__global__ __launch_bounds__(256) void topk_kernel(float* __restrict__ out, int out_size)
{
    __shared__ unsigned su[OFEAT];
    __shared__ unsigned hist[256];
    __shared__ unsigned long long cand[256];
    __shared__ unsigned sh_prefix;
    __shared__ int sh_need;
    __shared__ int ncand;

    const int b = blockIdx.x;
    const int tid = threadIdx.x;

    for (int o4 = tid; o4 < OFEAT / 4; o4 += 256) {
        float4 v = reinterpret_cast<const float4*>(g_y + (size_t)b * OFEAT)[o4];
        su[o4 * 4 + 0] = f2u(v.x);
        su[o4 * 4 + 1] = f2u(v.y);
        su[o4 * 4 + 2] = f2u(v.z);
        su[o4 * 4 + 3] = f2u(v.w);
    }

    unsigned prefix = 0, mask = 0;
    int shift = 24, need = KSEL;
    for (int pass = 0; pass < 4; ++pass) {
        hist[tid] = 0;
        __syncthreads();
        for (int o = tid; o < OFEAT; o += 256) {
            unsigned u = su[o];
            if ((u & mask) == prefix)
                atomicAdd(&hist[(u >> shift) & 255], 1u);
        }
        __syncthreads();
        if (tid == 0) {
            int cum = 0;
            for (int bin = 255; bin >= 0; --bin) {
                cum += (int)hist[bin];
                if (cum >= need) {
                    sh_prefix = prefix | ((unsigned)bin << shift);
                    sh_need   = need - (cum - (int)hist[bin]);
                    break;
                }
            }
        }
        __syncthreads();
        prefix = sh_prefix;
        need   = sh_need;
        mask  |= (0xFFu << shift);
        shift -= 8;
    }
    const unsigned T = prefix;

    if (tid == 0) ncand = 0;
    cand[tid] = 0ull;
    __syncthreads();
    for (int o = tid; o < OFEAT; o += 256) {
        unsigned u = su[o];
        if (u >= T) {
            int p = atomicAdd(&ncand, 1);
            if (p < 256)
                cand[p] = ((unsigned long long)u << 32) | (unsigned)(4095 - o);
        }
    }
    __syncthreads();

    for (int k2 = 2; k2 <= 256; k2 <<= 1) {
        for (int j2 = k2 >> 1; j2 > 0; j2 >>= 1) {
            int i = tid, ixj = tid ^ j2;
            if (ixj > i) {
                bool desc = ((i & k2) == 0);
                unsigned long long a = cand[i], bb = cand[ixj];
                if (desc ? (a < bb) : (a > bb)) { cand[i] = bb; cand[ixj] = a; }
            }
            __syncthreads();
        }
    }

    if (tid < KSEL) {
        unsigned long long key = cand[tid];
        unsigned u = (unsigned)(key >> 32);
        int o = 4095 - (int)(key & 0xFFFFFFFFull);
        int half = out_size >> 1;
        out[(size_t)b * KSEL + tid]        = u2f(u);
        out[(size_t)half + b * KSEL + tid] = (float)o;
    }
}

// ---------------------------------------------------------------------------
extern "C" void kernel_launch(void* const* d_in, const int* in_sizes, int n_in,
                              void* d_out, int out_size)
{
    const float* input  = nullptr;
    const float* weight = nullptr;
    const float* bias   = nullptr;
    const int*   idx    = nullptr;
    for (int i = 0; i < n_in; ++i) {
        if (in_sizes[i] == OFEAT * IFEAT)      weight = (const float*)d_in[i];
        else if (in_sizes[i] == OFEAT)         bias   = (const float*)d_in[i];
        else if (in_sizes[i] == BATCH * KSEL) {
            if (!input) input = (const float*)d_in[i];
            else        idx   = (const int*)d_in[i];
        }
    }

    prep_kernel<<<(BATCH * KSEL) / 256, 256>>>(input, idx);

    transpose_kernel<<<dim3(IFEAT / 64, GEMV_OUTS / 64), 256>>>(weight);

    cudaFuncSetAttribute(main_kernel,
                         cudaFuncAttributeMaxDynamicSharedMemorySize,
                         DYN_SMEM);
    main_kernel<<<GRID_X, 512, DYN_SMEM>>>(weight, input, idx, bias);

    topk_kernel<<<BATCH, 256>>>((float*)d_out, out_size);
}

// round 7
// speedup vs baseline: 1.3523x; 1.0599x over previous
#include <cuda_runtime.h>
#include <stdint.h>

#define BATCH 1024
#define KSEL  64
#define IFEAT 4096
#define OFEAT 4096

#define SM_OUTS   2048                 // outputs via smem path
#define NTILES    (SM_OUTS / 8)        // 256 blocks, tile = 8 outputs
#define GEMV_F4_BASE (SM_OUTS / 4)     // 512: first float4 index of gemv range
#define DYN_SMEM  (131072 + 16384)     // slab 128KB + ent stage 16KB

// Static device scratch (no runtime alloc).
__device__ float g_WT[(size_t)IFEAT * OFEAT];   // only cols >= SM_OUTS filled
__device__ float g_y[(size_t)BATCH * OFEAT];
__device__ uint2 g_ent[(size_t)KSEL * BATCH];   // k-major: [k*1024 + b] = (x bits, (c<<3)|((c>>2)&7))

// ---------------------------------------------------------------------------
// Prep: k-major entries. ev.y encodes slab word base (8c) | swizzle salt.
// ---------------------------------------------------------------------------
__global__ __launch_bounds__(512) void prep_kernel(const float* __restrict__ x,
                                                   const int*   __restrict__ idx)
{
    int t = blockIdx.x * 512 + threadIdx.x;   // t = k*1024 + b (write-coalesced)
    if (t >= BATCH * KSEL) return;
    int k = t >> 10, b = t & 1023;
    unsigned c = (unsigned)idx[b * KSEL + k];
    g_ent[t] = make_uint2(__float_as_uint(x[b * KSEL + k]),
                          (c << 3) | ((c >> 2) & 7u));
}

// ---------------------------------------------------------------------------
// Transpose W rows [SM_OUTS, 4096) -> WT (gemv share only). float4 both sides.
// ---------------------------------------------------------------------------
__global__ __launch_bounds__(256) void transpose_kernel(const float* __restrict__ W)
{
    __shared__ float t[64][65];
    const int bc = blockIdx.x * 64;
    const int br = SM_OUTS + blockIdx.y * 64;
    const int tid = threadIdx.x;
    const int sub = tid & 15;
    const int grp = tid >> 4;
#pragma unroll
    for (int p = 0; p < 4; ++p) {
        int row = p * 16 + grp;
        int c4  = sub * 4;
        float4 v = *reinterpret_cast<const float4*>(
            W + (size_t)(br + row) * IFEAT + bc + c4);
        t[c4 + 0][row] = v.x;
        t[c4 + 1][row] = v.y;
        t[c4 + 2][row] = v.z;
        t[c4 + 3][row] = v.w;
    }
    __syncthreads();
#pragma unroll
    for (int p = 0; p < 4; ++p) {
        int c  = p * 16 + grp;
        int o4 = sub * 4;
        float4 v = make_float4(t[c][o4], t[c][o4 + 1], t[c][o4 + 2], t[c][o4 + 3]);
        *reinterpret_cast<float4*>(g_WT + (size_t)(bc + c) * OFEAT + br + o4) = v;
    }
}

// ---------------------------------------------------------------------------
// Warp-specialized main kernel. Block i: smem tile i (outputs 8i..8i+7, all
// 1024 samples) on warps 0-7 + gemv for samples 4i..4i+3, outputs [2048,4096)
// on warps 8-15. Both paths: sequential-k FMA chain, bias last (bit-exact).
// ---------------------------------------------------------------------------
__global__ __launch_bounds__(512, 1) void main_kernel(const float* __restrict__ W,
                                                      const float* __restrict__ bias)
{
    extern __shared__ char smem_raw[];
    float* slab = reinterpret_cast<float*>(smem_raw);            // 32768 floats
    uint2* ents = reinterpret_cast<uint2*>(smem_raw + 131072);   // 2048 uint2

    const int bid = blockIdx.x;
    const int t   = threadIdx.x;
    const int o0  = bid * 8;

    // Stage slab with all 512 threads: coalesced LDG, conflict-free swizzled STS.
#pragma unroll 4
    for (int i = 0; i < 64; ++i) {
        int id = i * 512 + t;
        int r  = id >> 12;               // 0..7
        int c  = id & 4095;
        slab[(c << 3) | ((r ^ (c >> 2)) & 7)] = W[(size_t)(o0 + r) * IFEAT + c];
    }
    __syncthreads();

    const int warp = t >> 5;
    const int lane = t & 31;

    if (warp < 8) {
        // ---- smem path: 8 warps, 32 passes x 32 samples ----
        const unsigned r = (unsigned)(lane & 7);   // output within tile
        const int grp = lane >> 3;                 // sample slot (0..3)
        const int si  = warp * 4 + grp;            // 0..31
        const float bv = bias[o0 + (int)r];

        for (int pass = 0; pass < 32; ++pass) {
            const int s0 = pass * 32;
            // Stage 32 samples x 64 entries, k-major, by the 256 smem threads.
#pragma unroll
            for (int j = 0; j < 8; ++j) {
                int id = j * 256 + t;
                int k  = id >> 5, ss = id & 31;
                ents[(k << 5) + ss] = g_ent[(size_t)k * BATCH + s0 + ss];
            }
            asm volatile("bar.sync 1, 256;" ::: "memory");

            float a = 0.f;
#pragma unroll 8
            for (int k = 0; k < KSEL; ++k) {
                uint2 ev = ents[(k << 5) + si];
                a = fmaf(__uint_as_float(ev.x), slab[ev.y ^ r], a);
            }
            g_y[(size_t)(s0 + si) * OFEAT + o0 + (int)r] = a + bv;

            asm volatile("bar.sync 1, 256;" ::: "memory");
        }
    } else {
        // ---- gemv path: 8 warps, 2 warps per sample, LTS-saturating ----
        const int local = warp - 8;
        const int b     = bid * 4 + (local >> 1);
        const int f4b   = GEMV_F4_BASE + (local & 1) * 256 + lane;  // + j*32

        float4 acc[8];
#pragma unroll
        for (int j = 0; j < 8; ++j) acc[j] = make_float4(0.f, 0.f, 0.f, 0.f);

#pragma unroll 4
        for (int k = 0; k < KSEL; ++k) {
            uint2 ev = g_ent[(size_t)k * BATCH + b];     // warp-uniform
            const float xv = __uint_as_float(ev.x);
            const float4* wp = reinterpret_cast<const float4*>(
                g_WT + (size_t)(ev.y >> 3) * OFEAT) + f4b;   // c = ev.y >> 3 (FIXED)
#pragma unroll
            for (int j = 0; j < 8; ++j) {
                float4 w = wp[j * 32];
                acc[j].x = fmaf(xv, w.x, acc[j].x);
                acc[j].y = fmaf(xv, w.y, acc[j].y);
                acc[j].z = fmaf(xv, w.z, acc[j].z);
                acc[j].w = fmaf(xv, w.w, acc[j].w);
            }
        }
        const float4* bp = reinterpret_cast<const float4*>(bias) + f4b;
        float4* yp = reinterpret_cast<float4*>(g_y + (size_t)b * OFEAT) + f4b;
#pragma unroll
        for (int j = 0; j < 8; ++j) {
            float4 bb = bp[j * 32];
            yp[j * 32] = make_float4(acc[j].x + bb.x, acc[j].y + bb.y,
                                     acc[j].z + bb.z, acc[j].w + bb.w);
        }
    }
}

// ---------------------------------------------------------------------------
// Exact top-64 (proven semantics), 512 threads + warp-parallel bin selection.
// ---------------------------------------------------------------------------
__device__ __forceinline__ unsigned f2u(float f) {
    unsigned u = __float_as_uint(f);
    return (u & 0x80000000u) ? ~u : (u | 0x80000000u);
}
__device__ __forceinline__ float u2f(unsigned u) {
    unsigned b = (u & 0x80000000u) ? (u ^ 0x80000000u) : ~u;
    return __uint_as_float(b);
}

__global__ __launch_bounds__(512) void topk_kernel(float* __restrict__ out, int out_size)
{
    __shared__ unsigned su[OFEAT];
    __shared__ unsigned hist[256];
    __shared__ unsigned long long cand[256];
    __shared__ unsigned sh_prefix;
    __shared__ int sh_need;
    __shared__ int ncand;

    const int b = blockIdx.x;
    const int tid = threadIdx.x;
    const int warp = tid >> 5, lane = tid & 31;

    for (int o4 = tid; o4 < OFEAT / 4; o4 += 512) {
        float4 v = reinterpret_cast<const float4*>(g_y + (size_t)b * OFEAT)[o4];
        su[o4 * 4 + 0] = f2u(v.x);
        su[o4 * 4 + 1] = f2u(v.y);
        su[o4 * 4 + 2] = f2u(v.z);
        su[o4 * 4 + 3] = f2u(v.w);
    }

    unsigned prefix = 0, mask = 0;
    int shift = 24, need = KSEL;
    for (int pass = 0; pass < 4; ++pass) {
        if (tid < 256) hist[tid] = 0;
        __syncthreads();
        for (int o = tid; o < OFEAT; o += 512) {
            unsigned u = su[o];
            if ((u & mask) == prefix)
                atomicAdd(&hist[(u >> shift) & 255], 1u);
        }
        __syncthreads();
        if (warp == 0) {
            int s = 0;
#pragma unroll
            for (int j = 0; j < 8; ++j) s += (int)hist[lane * 8 + j];
            int S = s;
#pragma unroll
            for (int off = 1; off < 32; off <<= 1) {
                int v = __shfl_down_sync(0xFFFFFFFFu, S, off);
                if (lane + off < 32) S += v;
            }
            int Snext = __shfl_down_sync(0xFFFFFFFFu, S, 1);
            if (lane == 31) Snext = 0;
            unsigned m = __ballot_sync(0xFFFFFFFFu, S >= need);
            int lc = 31 - __clz(m);     // S decreasing in lane; max lane with S>=need
            if (lane == lc) {
                int cum = Snext;
                for (int bin = lc * 8 + 7; bin >= lc * 8; --bin) {
                    cum += (int)hist[bin];
                    if (cum >= need) {
                        sh_prefix = prefix | ((unsigned)bin << shift);
                        sh_need   = need - (cum - (int)hist[bin]);
                        break;
                    }
                }
            }
        }
        __syncthreads();
        prefix = sh_prefix;
        need   = sh_need;
        mask  |= (0xFFu << shift);
        shift -= 8;
    }
    const unsigned T = prefix;

    if (tid == 0) ncand = 0;
    if (tid < 256) cand[tid] = 0ull;
    __syncthreads();
    for (int o = tid; o < OFEAT; o += 512) {
        unsigned u = su[o];
        if (u >= T) {
            int p = atomicAdd(&ncand, 1);
            if (p < 256)
                cand[p] = ((unsigned long long)u << 32) | (unsigned)(4095 - o);
        }
    }
    __syncthreads();

    for (int k2 = 2; k2 <= 256; k2 <<= 1) {
        for (int j2 = k2 >> 1; j2 > 0; j2 >>= 1) {
            if (tid < 256) {
                int i = tid, ixj = tid ^ j2;
                if (ixj > i) {
                    bool desc = ((i & k2) == 0);
                    unsigned long long a = cand[i], bb = cand[ixj];
                    if (desc ? (a < bb) : (a > bb)) { cand[i] = bb; cand[ixj] = a; }
                }
            }
            __syncthreads();
        }
    }

    if (tid < KSEL) {
        unsigned long long key = cand[tid];
        unsigned u = (unsigned)(key >> 32);
        int o = 4095 - (int)(key & 0xFFFFFFFFull);
        int half = out_size >> 1;
        out[(size_t)b * KSEL + tid]        = u2f(u);
        out[(size_t)half + b * KSEL + tid] = (float)o;
    }
}

// ---------------------------------------------------------------------------
extern "C" void kernel_launch(void* const* d_in, const int* in_sizes, int n_in,
                              void* d_out, int out_size)
{
    const float* input  = nullptr;
    const float* weight = nullptr;
    const float* bias   = nullptr;
    const int*   idx    = nullptr;
    for (int i = 0; i < n_in; ++i) {
        if (in_sizes[i] == OFEAT * IFEAT)      weight = (const float*)d_in[i];
        else if (in_sizes[i] == OFEAT)         bias   = (const float*)d_in[i];
        else if (in_sizes[i] == BATCH * KSEL) {
            if (!input) input = (const float*)d_in[i];
            else        idx   = (const int*)d_in[i];
        }
    }

    prep_kernel<<<(BATCH * KSEL) / 512, 512>>>(input, idx);

    transpose_kernel<<<dim3(IFEAT / 64, (OFEAT - SM_OUTS) / 64), 256>>>(weight);

    cudaFuncSetAttribute(main_kernel,
                         cudaFuncAttributeMaxDynamicSharedMemorySize,
                         DYN_SMEM);
    main_kernel<<<NTILES, 512, DYN_SMEM>>>(weight, bias);

    topk_kernel<<<BATCH, 512>>>((float*)d_out, out_size);
}

// round 8
// speedup vs baseline: 1.5945x; 1.1791x over previous
#include <cuda_runtime.h>
#include <stdint.h>

#define BATCH 1024
#define KSEL  64
#define IFEAT 4096
#define OFEAT 4096

#define SM_OUTS   2048                 // outputs via smem path
#define NTILES    (SM_OUTS / 8)        // 256 blocks, tile = 8 outputs
#define GEMV_F4_BASE (SM_OUTS / 4)     // 512: first float4 index of gemv range
#define ENTBUF    4096                 // uint2 per ent buffer (64 samples x 64 k)
#define DYN_SMEM  (131072 + 2 * ENTBUF * 8)   // slab 128KB + 2x32KB ent buffers

// Static device scratch (no runtime alloc).
__device__ float g_WT[(size_t)IFEAT * OFEAT];   // only cols >= SM_OUTS filled
__device__ float g_y[(size_t)BATCH * OFEAT];
__device__ uint2 g_ent[(size_t)KSEL * BATCH];   // k-major: [k*1024 + b] = (x bits, (c<<3)|((c>>2)&7))

// ---------------------------------------------------------------------------
// Prep: k-major entries. ev.y encodes slab word base (8c) | swizzle salt.
// ---------------------------------------------------------------------------
__global__ __launch_bounds__(512) void prep_kernel(const float* __restrict__ x,
                                                   const int*   __restrict__ idx)
{
    int t = blockIdx.x * 512 + threadIdx.x;   // t = k*1024 + b (write-coalesced)
    if (t >= BATCH * KSEL) return;
    int k = t >> 10, b = t & 1023;
    unsigned c = (unsigned)idx[b * KSEL + k];
    g_ent[t] = make_uint2(__float_as_uint(x[b * KSEL + k]),
                          (c << 3) | ((c >> 2) & 7u));
}

// ---------------------------------------------------------------------------
// Transpose W rows [SM_OUTS, 4096) -> WT (gemv share only). float4 both sides.
// ---------------------------------------------------------------------------
__global__ __launch_bounds__(256) void transpose_kernel(const float* __restrict__ W)
{
    __shared__ float t[64][65];
    const int bc = blockIdx.x * 64;
    const int br = SM_OUTS + blockIdx.y * 64;
    const int tid = threadIdx.x;
    const int sub = tid & 15;
    const int grp = tid >> 4;
#pragma unroll
    for (int p = 0; p < 4; ++p) {
        int row = p * 16 + grp;
        int c4  = sub * 4;
        float4 v = *reinterpret_cast<const float4*>(
            W + (size_t)(br + row) * IFEAT + bc + c4);
        t[c4 + 0][row] = v.x;
        t[c4 + 1][row] = v.y;
        t[c4 + 2][row] = v.z;
        t[c4 + 3][row] = v.w;
    }
    __syncthreads();
#pragma unroll
    for (int p = 0; p < 4; ++p) {
        int c  = p * 16 + grp;
        int o4 = sub * 4;
        float4 v = make_float4(t[c][o4], t[c][o4 + 1], t[c][o4 + 2], t[c][o4 + 3]);
        *reinterpret_cast<float4*>(g_WT + (size_t)(bc + c) * OFEAT + br + o4) = v;
    }
}

// ---------------------------------------------------------------------------
// Warp-specialized main kernel. Block i: smem tile i (outputs 8i..8i+7, all
// 1024 samples) on warps 0-7 + gemv for samples 4i..4i+3, outputs [2048,4096)
// on warps 8-15. Both paths: sequential-k FMA chain, bias last (bit-exact).
// smem path: 2 acc chains/lane, double-buffered entry staging (LDG prefetch
// to regs, STS after barrier) -> crossbar-capacity bound, not latency bound.
// ---------------------------------------------------------------------------
__global__ __launch_bounds__(512, 1) void main_kernel(const float* __restrict__ W,
                                                      const float* __restrict__ bias)
{
    extern __shared__ char smem_raw[];
    float* slab = reinterpret_cast<float*>(smem_raw);            // 32768 floats
    uint2* ebuf = reinterpret_cast<uint2*>(smem_raw + 131072);   // 2 x 4096 uint2

    const int bid = blockIdx.x;
    const int t   = threadIdx.x;
    const int o0  = bid * 8;

    // Stage slab with all 512 threads: coalesced LDG, conflict-free swizzled STS.
#pragma unroll 4
    for (int i = 0; i < 64; ++i) {
        int id = i * 512 + t;
        int r  = id >> 12;               // 0..7
        int c  = id & 4095;
        slab[(c << 3) | ((r ^ (c >> 2)) & 7)] = W[(size_t)(o0 + r) * IFEAT + c];
    }
    __syncthreads();

    const int warp = t >> 5;
    const int lane = t & 31;

    if (warp < 8) {
        // ---- smem path: 8 warps, 16 passes x 64 samples, 2 chains/lane ----
        const unsigned r = (unsigned)(lane & 7);
        const int grp = lane >> 3;
        const int ss0 = warp * 4 + grp;        // 0..31
        const int ss1 = ss0 + 32;              // 32..63
        const float bv = bias[o0 + (int)r];

        // Prologue: stage pass 0 entries (64 samples x 64 k, k-major).
#pragma unroll
        for (int j = 0; j < 16; ++j) {
            int id = j * 256 + t;
            int k  = id >> 6, ss = id & 63;
            ebuf[id] = g_ent[(size_t)k * BATCH + ss];
        }
        asm volatile("bar.sync 1, 256;" ::: "memory");

        for (int pass = 0; pass < 16; ++pass) {
            const uint2* cur = ebuf + (pass & 1) * ENTBUF;
            uint2* nxt = ebuf + ((pass + 1) & 1) * ENTBUF;
            const int s0 = pass * 64;

            // Prefetch next pass's entries into registers (no smem use yet).
            uint2 pf[16];
            if (pass < 15) {
                const int ns0 = s0 + 64;
#pragma unroll
                for (int j = 0; j < 16; ++j) {
                    int id = j * 256 + t;
                    pf[j] = __ldg(&g_ent[(size_t)(id >> 6) * BATCH + ns0 + (id & 63)]);
                }
            }

            float a0 = 0.f, a1 = 0.f;
#pragma unroll 8
            for (int k = 0; k < KSEL; ++k) {
                uint2 e0 = cur[(k << 6) + ss0];
                uint2 e1 = cur[(k << 6) + ss1];
                a0 = fmaf(__uint_as_float(e0.x), slab[e0.y ^ r], a0);
                a1 = fmaf(__uint_as_float(e1.x), slab[e1.y ^ r], a1);
            }
            g_y[(size_t)(s0 + ss0) * OFEAT + o0 + (int)r] = a0 + bv;
            g_y[(size_t)(s0 + ss1) * OFEAT + o0 + (int)r] = a1 + bv;

            asm volatile("bar.sync 1, 256;" ::: "memory");
            if (pass < 15) {
#pragma unroll
                for (int j = 0; j < 16; ++j)
                    nxt[j * 256 + t] = pf[j];
            }
            asm volatile("bar.sync 1, 256;" ::: "memory");
        }
    } else {
        // ---- gemv path: 8 warps, 2 warps per sample, LTS-saturating ----
        const int local = warp - 8;
        const int b     = bid * 4 + (local >> 1);
        const int f4b   = GEMV_F4_BASE + (local & 1) * 256 + lane;  // + j*32

        float4 acc[8];
#pragma unroll
        for (int j = 0; j < 8; ++j) acc[j] = make_float4(0.f, 0.f, 0.f, 0.f);

#pragma unroll 4
        for (int k = 0; k < KSEL; ++k) {
            uint2 ev = g_ent[(size_t)k * BATCH + b];     // warp-uniform
            const float xv = __uint_as_float(ev.x);
            const float4* wp = reinterpret_cast<const float4*>(
                g_WT + (size_t)(ev.y >> 3) * OFEAT) + f4b;
#pragma unroll
            for (int j = 0; j < 8; ++j) {
                float4 w = wp[j * 32];
                acc[j].x = fmaf(xv, w.x, acc[j].x);
                acc[j].y = fmaf(xv, w.y, acc[j].y);
                acc[j].z = fmaf(xv, w.z, acc[j].z);
                acc[j].w = fmaf(xv, w.w, acc[j].w);
            }
        }
        const float4* bp = reinterpret_cast<const float4*>(bias) + f4b;
        float4* yp = reinterpret_cast<float4*>(g_y + (size_t)b * OFEAT) + f4b;
#pragma unroll
        for (int j = 0; j < 8; ++j) {
            float4 bb = bp[j * 32];
            yp[j * 32] = make_float4(acc[j].x + bb.x, acc[j].y + bb.y,
                                     acc[j].z + bb.z, acc[j].w + bb.w);
        }
    }
}

// ---------------------------------------------------------------------------
// Exact top-64 v2: register-resident values (8/thread), 2 radix passes
// (8+8 bits), candidates = all u with top-16 bits >= selected prefix
// (provably <= ~80), stable bitonic-256 (value desc, index asc).
// ---------------------------------------------------------------------------
__device__ __forceinline__ unsigned f2u(float f) {
    unsigned u = __float_as_uint(f);
    return (u & 0x80000000u) ? ~u : (u | 0x80000000u);
}
__device__ __forceinline__ float u2f(unsigned u) {
    unsigned b = (u & 0x80000000u) ? (u ^ 0x80000000u) : ~u;
    return __uint_as_float(b);
}

__global__ __launch_bounds__(512) void topk_kernel(float* __restrict__ out, int out_size)
{
    __shared__ unsigned hist[256];
    __shared__ unsigned long long cand[256];
    __shared__ unsigned sh_bin;
    __shared__ int sh_need;
    __shared__ int ncand;

    const int b = blockIdx.x;
    const int tid = threadIdx.x;
    const int warp = tid >> 5, lane = tid & 31;

    // Load 8 values into registers (outputs tid*8 .. tid*8+7).
    unsigned u[8];
    {
        const float4* yp = reinterpret_cast<const float4*>(g_y + (size_t)b * OFEAT) + tid * 2;
        float4 v0 = yp[0], v1 = yp[1];
        u[0] = f2u(v0.x); u[1] = f2u(v0.y); u[2] = f2u(v0.z); u[3] = f2u(v0.w);
        u[4] = f2u(v1.x); u[5] = f2u(v1.y); u[6] = f2u(v1.z); u[7] = f2u(v1.w);
    }

    unsigned prefix = 0;   // accumulated high bits
    int need = KSEL;

#pragma unroll
    for (int pass = 0; pass < 2; ++pass) {
        const int shift = 24 - pass * 8;
        if (tid < 256) hist[tid] = 0;
        __syncthreads();
        if (pass == 0) {
#pragma unroll
            for (int j = 0; j < 8; ++j)
                atomicAdd(&hist[u[j] >> 24], 1u);
        } else {
#pragma unroll
            for (int j = 0; j < 8; ++j)
                if ((u[j] >> 24) == prefix)
                    atomicAdd(&hist[(u[j] >> 16) & 255], 1u);
        }
        __syncthreads();
        if (warp == 0) {
            int s = 0;
#pragma unroll
            for (int j = 0; j < 8; ++j) s += (int)hist[lane * 8 + j];
            int S = s;
#pragma unroll
            for (int off = 1; off < 32; off <<= 1) {
                int v = __shfl_down_sync(0xFFFFFFFFu, S, off);
                if (lane + off < 32) S += v;
            }
            int Snext = __shfl_down_sync(0xFFFFFFFFu, S, 1);
            if (lane == 31) Snext = 0;
            unsigned m = __ballot_sync(0xFFFFFFFFu, S >= need);
            int lc = 31 - __clz(m);
            if (lane == lc) {
                int cum = Snext;
                for (int bin = lc * 8 + 7; bin >= lc * 8; --bin) {
                    cum += (int)hist[bin];
                    if (cum >= need) {
                        sh_bin  = (unsigned)bin;
                        sh_need = need - (cum - (int)hist[bin]);
                        break;
                    }
                }
            }
        }
        __syncthreads();
        prefix = (prefix << 8) | sh_bin;   // pass0: 8-bit; pass1: 16-bit
        need   = sh_need;
        __syncthreads();
    }
    const unsigned P16 = prefix;   // 16-bit prefix containing rank-64 element

    // Collect all u with (u>>16) >= P16  (<= ~80 candidates, buffer 256).
    if (tid == 0) ncand = 0;
    if (tid < 256) cand[tid] = 0ull;
    __syncthreads();
#pragma unroll
    for (int j = 0; j < 8; ++j) {
        if ((u[j] >> 16) >= P16) {
            int p = atomicAdd(&ncand, 1);
            if (p < 256) {
                int o = tid * 8 + j;
                cand[p] = ((unsigned long long)u[j] << 32) | (unsigned)(4095 - o);
            }
        }
    }
    __syncthreads();

    // Bitonic sort 256 keys descending (value desc, index asc on ties).
    for (int k2 = 2; k2 <= 256; k2 <<= 1) {
        for (int j2 = k2 >> 1; j2 > 0; j2 >>= 1) {
            if (tid < 256) {
                int i = tid, ixj = tid ^ j2;
                if (ixj > i) {
                    bool desc = ((i & k2) == 0);
                    unsigned long long a = cand[i], bb = cand[ixj];
                    if (desc ? (a < bb) : (a > bb)) { cand[i] = bb; cand[ixj] = a; }
                }
            }
            __syncthreads();
        }
    }

    if (tid < KSEL) {
        unsigned long long key = cand[tid];
        unsigned uu = (unsigned)(key >> 32);
        int o = 4095 - (int)(key & 0xFFFFFFFFull);
        int half = out_size >> 1;
        out[(size_t)b * KSEL + tid]        = u2f(uu);
        out[(size_t)half + b * KSEL + tid] = (float)o;
    }
}

// ---------------------------------------------------------------------------
extern "C" void kernel_launch(void* const* d_in, const int* in_sizes, int n_in,
                              void* d_out, int out_size)
{
    const float* input  = nullptr;
    const float* weight = nullptr;
    const float* bias   = nullptr;
    const int*   idx    = nullptr;
    for (int i = 0; i < n_in; ++i) {
        if (in_sizes[i] == OFEAT * IFEAT)      weight = (const float*)d_in[i];
        else if (in_sizes[i] == OFEAT)         bias   = (const float*)d_in[i];
        else if (in_sizes[i] == BATCH * KSEL) {
            if (!input) input = (const float*)d_in[i];
            else        idx   = (const int*)d_in[i];
        }
    }

    prep_kernel<<<(BATCH * KSEL) / 512, 512>>>(input, idx);

    transpose_kernel<<<dim3(IFEAT / 64, (OFEAT - SM_OUTS) / 64), 256>>>(weight);

    cudaFuncSetAttribute(main_kernel,
                         cudaFuncAttributeMaxDynamicSharedMemorySize,
                         DYN_SMEM);
    main_kernel<<<NTILES, 512, DYN_SMEM>>>(weight, bias);

    topk_kernel<<<BATCH, 512>>>((float*)d_out, out_size);
}

// round 9
// speedup vs baseline: 2.3453x; 1.4709x over previous
#include <cuda_runtime.h>
#include <stdint.h>

#define BATCH 1024
#define KSEL  64
#define IFEAT 4096
#define OFEAT 4096

// Static device scratch (no runtime alloc).
__device__ float g_WT[(size_t)IFEAT * OFEAT];   // 64 MB, W transposed
__device__ float g_y[(size_t)BATCH * OFEAT];    // 16 MB

// ---------------------------------------------------------------------------
// Transpose W (O,I) -> WT (I,O). 64x64 tiles, float4 on both global sides.
// ---------------------------------------------------------------------------
__global__ __launch_bounds__(256) void transpose_kernel(const float* __restrict__ W)
{
    __shared__ float t[64][65];
    const int bc = blockIdx.x * 64;   // input-feature (column of W)
    const int br = blockIdx.y * 64;   // output-feature (row of W)
    const int tid = threadIdx.x;
    const int sub = tid & 15;
    const int grp = tid >> 4;
#pragma unroll
    for (int p = 0; p < 4; ++p) {
        int row = p * 16 + grp;
        int c4  = sub * 4;
        float4 v = *reinterpret_cast<const float4*>(
            W + (size_t)(br + row) * IFEAT + bc + c4);
        t[c4 + 0][row] = v.x;
        t[c4 + 1][row] = v.y;
        t[c4 + 2][row] = v.z;
        t[c4 + 3][row] = v.w;
    }
    __syncthreads();
#pragma unroll
    for (int p = 0; p < 4; ++p) {
        int c  = p * 16 + grp;
        int o4 = sub * 4;
        float4 v = make_float4(t[c][o4], t[c][o4 + 1], t[c][o4 + 2], t[c][o4 + 3]);
        *reinterpret_cast<float4*>(g_WT + (size_t)(bc + c) * OFEAT + br + o4) = v;
    }
}

// ---------------------------------------------------------------------------
// Batched sparse gemv: y[b,o] = (sum_{k seq} x[b,k]*WT[c_k][o]) + bias[o].
// One float4 of outputs per thread, 1024 outs/block, full occupancy.
// Exact sequential-k FMA chain, bias last (bit-exact vs reference).
// ---------------------------------------------------------------------------
__global__ __launch_bounds__(256) void gemv_kernel(const float* __restrict__ x,
                                                   const int*   __restrict__ idx,
                                                   const float* __restrict__ bias)
{
    __shared__ float sx[KSEL];
    __shared__ int   soff[KSEL];

    const int b = blockIdx.y;
    const int o = blockIdx.x * 1024 + threadIdx.x * 4;

    if (threadIdx.x < KSEL) {
        sx[threadIdx.x]   = x[b * KSEL + threadIdx.x];
        soff[threadIdx.x] = idx[b * KSEL + threadIdx.x] * OFEAT;
    }
    __syncthreads();

    float4 a = make_float4(0.f, 0.f, 0.f, 0.f);
#pragma unroll 8
    for (int k = 0; k < KSEL; ++k) {
        const float xv = sx[k];
        const float4 w = *reinterpret_cast<const float4*>(g_WT + soff[k] + o);
        a.x = fmaf(xv, w.x, a.x);
        a.y = fmaf(xv, w.y, a.y);
        a.z = fmaf(xv, w.z, a.z);
        a.w = fmaf(xv, w.w, a.w);
    }
    const float4 bb = *reinterpret_cast<const float4*>(bias + o);
    *reinterpret_cast<float4*>(g_y + (size_t)b * OFEAT + o) =
        make_float4(a.x + bb.x, a.y + bb.y, a.z + bb.z, a.w + bb.w);
}

// ---------------------------------------------------------------------------
// Exact top-64 v2 (measured 24.1us): register-resident values, 2 radix passes
// (8+8 bits), candidates = all u with top-16 bits >= prefix, stable bitonic.
// ---------------------------------------------------------------------------
__device__ __forceinline__ unsigned f2u(float f) {
    unsigned u = __float_as_uint(f);
    return (u & 0x80000000u) ? ~u : (u | 0x80000000u);
}
__device__ __forceinline__ float u2f(unsigned u) {
    unsigned b = (u & 0x80000000u) ? (u ^ 0x80000000u) : ~u;
    return __uint_as_float(b);
}

__global__ __launch_bounds__(512) void topk_kernel(float* __restrict__ out, int out_size)
{
    __shared__ unsigned hist[256];
    __shared__ unsigned long long cand[256];
    __shared__ unsigned sh_bin;
    __shared__ int sh_need;
    __shared__ int ncand;

    const int b = blockIdx.x;
    const int tid = threadIdx.x;
    const int warp = tid >> 5, lane = tid & 31;

    unsigned u[8];
    {
        const float4* yp = reinterpret_cast<const float4*>(g_y + (size_t)b * OFEAT) + tid * 2;
        float4 v0 = yp[0], v1 = yp[1];
        u[0] = f2u(v0.x); u[1] = f2u(v0.y); u[2] = f2u(v0.z); u[3] = f2u(v0.w);
        u[4] = f2u(v1.x); u[5] = f2u(v1.y); u[6] = f2u(v1.z); u[7] = f2u(v1.w);
    }

    unsigned prefix = 0;
    int need = KSEL;

#pragma unroll
    for (int pass = 0; pass < 2; ++pass) {
        if (tid < 256) hist[tid] = 0;
        __syncthreads();
        if (pass == 0) {
#pragma unroll
            for (int j = 0; j < 8; ++j)
                atomicAdd(&hist[u[j] >> 24], 1u);
        } else {
#pragma unroll
            for (int j = 0; j < 8; ++j)
                if ((u[j] >> 24) == prefix)
                    atomicAdd(&hist[(u[j] >> 16) & 255], 1u);
        }
        __syncthreads();
        if (warp == 0) {
            int s = 0;
#pragma unroll
            for (int j = 0; j < 8; ++j) s += (int)hist[lane * 8 + j];
            int S = s;
#pragma unroll
            for (int off = 1; off < 32; off <<= 1) {
                int v = __shfl_down_sync(0xFFFFFFFFu, S, off);
                if (lane + off < 32) S += v;
            }
            int Snext = __shfl_down_sync(0xFFFFFFFFu, S, 1);
            if (lane == 31) Snext = 0;
            unsigned m = __ballot_sync(0xFFFFFFFFu, S >= need);
            int lc = 31 - __clz(m);
            if (lane == lc) {
                int cum = Snext;
                for (int bin = lc * 8 + 7; bin >= lc * 8; --bin) {
                    cum += (int)hist[bin];
                    if (cum >= need) {
                        sh_bin  = (unsigned)bin;
                        sh_need = need - (cum - (int)hist[bin]);
                        break;
                    }
                }
            }
        }
        __syncthreads();
        prefix = (prefix << 8) | sh_bin;
        need   = sh_need;
        __syncthreads();
    }
    const unsigned P16 = prefix;

    if (tid == 0) ncand = 0;
    if (tid < 256) cand[tid] = 0ull;
    __syncthreads();
#pragma unroll
    for (int j = 0; j < 8; ++j) {
        if ((u[j] >> 16) >= P16) {
            int p = atomicAdd(&ncand, 1);
            if (p < 256) {
                int o = tid * 8 + j;
                cand[p] = ((unsigned long long)u[j] << 32) | (unsigned)(4095 - o);
            }
        }
    }
    __syncthreads();

    for (int k2 = 2; k2 <= 256; k2 <<= 1) {
        for (int j2 = k2 >> 1; j2 > 0; j2 >>= 1) {
            if (tid < 256) {
                int i = tid, ixj = tid ^ j2;
                if (ixj > i) {
                    bool desc = ((i & k2) == 0);
                    unsigned long long a = cand[i], bb = cand[ixj];
                    if (desc ? (a < bb) : (a > bb)) { cand[i] = bb; cand[ixj] = a; }
                }
            }
            __syncthreads();
        }
    }

    if (tid < KSEL) {
        unsigned long long key = cand[tid];
        unsigned uu = (unsigned)(key >> 32);
        int o = 4095 - (int)(key & 0xFFFFFFFFull);
        int half = out_size >> 1;
        out[(size_t)b * KSEL + tid]        = u2f(uu);
        out[(size_t)half + b * KSEL + tid] = (float)o;
    }
}

// ---------------------------------------------------------------------------
extern "C" void kernel_launch(void* const* d_in, const int* in_sizes, int n_in,
                              void* d_out, int out_size)
{
    const float* input  = nullptr;
    const float* weight = nullptr;
    const float* bias   = nullptr;
    const int*   idx    = nullptr;
    for (int i = 0; i < n_in; ++i) {
        if (in_sizes[i] == OFEAT * IFEAT)      weight = (const float*)d_in[i];
        else if (in_sizes[i] == OFEAT)         bias   = (const float*)d_in[i];
        else if (in_sizes[i] == BATCH * KSEL) {
            if (!input) input = (const float*)d_in[i];
            else        idx   = (const int*)d_in[i];
        }
    }

    transpose_kernel<<<dim3(IFEAT / 64, OFEAT / 64), 256>>>(weight);
    gemv_kernel<<<dim3(OFEAT / 1024, BATCH), 256>>>(input, idx, bias);
    topk_kernel<<<BATCH, 512>>>((float*)d_out, out_size);
}